// round 1
// baseline (speedup 1.0000x reference)
#include <cuda_runtime.h>
#include <math.h>

// ---------------- scratch (no allocation allowed) ----------------
__device__ float g_hs[5000000];    // 50000 x 100
__device__ float g_acc0[5000000];
__device__ float g_acc1[5000000];
__device__ float g_deg[50048];
__device__ float g_dinv[50048];
__device__ float g_partials[512];
__device__ float g_norm2;

// ---------------- ||x||^2 reduction ----------------
__global__ void sumsq_partial_kernel(const float* __restrict__ x, long n) {
    float s = 0.f;
    long stride = (long)gridDim.x * blockDim.x;
    for (long i = (long)blockIdx.x * blockDim.x + threadIdx.x; i < n; i += stride) {
        float v = x[i];
        s += v * v;
    }
    __shared__ float sm[256];
    sm[threadIdx.x] = s;
    __syncthreads();
    for (int o = 128; o > 0; o >>= 1) {
        if (threadIdx.x < o) sm[threadIdx.x] += sm[threadIdx.x + o];
        __syncthreads();
    }
    if (threadIdx.x == 0) g_partials[blockIdx.x] = sm[0];
}

__global__ void sumsq_final_kernel(int nb) {
    __shared__ float sm[256];
    float s = 0.f;
    for (int i = threadIdx.x; i < nb; i += 256) s += g_partials[i];
    sm[threadIdx.x] = s;
    __syncthreads();
    for (int o = 128; o > 0; o >>= 1) {
        if (threadIdx.x < o) sm[threadIdx.x] += sm[threadIdx.x + o];
        __syncthreads();
    }
    if (threadIdx.x == 0) g_norm2 = sm[0];
}

// ---------------- degree / dinv ----------------
__global__ void deg_init_kernel(int n) {
    int i = blockIdx.x * blockDim.x + threadIdx.x;
    if (i < n) g_deg[i] = 1.0f;  // self-loop
}

__global__ void deg_count_kernel(const int* __restrict__ dst, int E) {
    int i = blockIdx.x * blockDim.x + threadIdx.x;
    if (i < E) atomicAdd(&g_deg[dst[i]], 1.0f);
}

__global__ void dinv_kernel(int n) {
    int i = blockIdx.x * blockDim.x + threadIdx.x;
    if (i < n) g_dinv[i] = 1.0f / sqrtf(g_deg[i]);
}

// ---------------- GCN GEMM: hs = rowscale * ((xf(X)) @ W); acc = hs ----------------
// Input transform (layer 1): xv = dinv[row]*X + bin[k]   (bin != nullptr)
// Output scale: dinv[row] * (use_norm ? rsqrt(norm2) : 1)
// 64 rows per block, 256 threads: thread = (ty row, tx 25-col group)
__global__ void gcn_gemm_kernel(const float* __restrict__ X, const float* __restrict__ W,
                                const float* __restrict__ bin, int use_norm,
                                float* __restrict__ hs, float* __restrict__ acc, int N) {
    extern __shared__ float smem[];
    float* sW = smem;          // 100*100 = 10000 floats
    float* sX = smem + 10000;  // 64*100  = 6400 floats
    int tid = threadIdx.x;
    int row0 = blockIdx.x * 64;

    for (int i = tid; i < 10000; i += 256) sW[i] = W[i];
    for (int i = tid; i < 6400; i += 256) {
        int r = i / 100, k = i - r * 100;
        int gr = row0 + r;
        float v = 0.f;
        if (gr < N) {
            v = X[(size_t)gr * 100 + k];
            if (bin) v = v * g_dinv[gr] + bin[k];
        }
        sX[i] = v;
    }
    __syncthreads();

    int tx = tid & 3, ty = tid >> 2;
    float a[25];
#pragma unroll
    for (int c = 0; c < 25; c++) a[c] = 0.f;
    const float* xrow = sX + ty * 100;
    const float* wcol = sW + tx * 25;
#pragma unroll 4
    for (int k = 0; k < 100; k++) {
        float xv = xrow[k];
#pragma unroll
        for (int c = 0; c < 25; c++) a[c] += xv * wcol[k * 100 + c];
    }

    int gr = row0 + ty;
    if (gr < N) {
        float s = g_dinv[gr];
        if (use_norm) s *= rsqrtf(g_norm2);
        size_t base = (size_t)gr * 100 + tx * 25;
#pragma unroll
        for (int c = 0; c < 25; c++) {
            float v = a[c] * s;
            hs[base + c] = v;
            acc[base + c] = v;
        }
    }
}

// ---------------- edge scatter: acc[dst] += hs[src] (100 floats = 25 float4) ----------------
__global__ void scatter_kernel(const float* __restrict__ hs, float* __restrict__ acc,
                               const int* __restrict__ src, const int* __restrict__ dst,
                               long total) {
    long i = (long)blockIdx.x * blockDim.x + threadIdx.x;
    if (i >= total) return;
    int e = (int)(i / 25);
    int c = (int)(i - (long)e * 25);
    int s = __ldg(src + e);
    int d = __ldg(dst + e);
    float4 v = __ldg((const float4*)(hs + (size_t)s * 100) + c);
    float4* p = (float4*)(acc + (size_t)d * 100) + c;
    asm volatile("red.global.add.v4.f32 [%0], {%1,%2,%3,%4};"
                 :: "l"(p), "f"(v.x), "f"(v.y), "f"(v.z), "f"(v.w)
                 : "memory");
}

// ---------------- MLP head: out[i] = relu(x1 @ lW0 + lb0) @ lW1 + lb1 ----------------
// x1[k] = dinv[i]*acc[i][k] + bconv[k]
__global__ void head_kernel(const float* __restrict__ acc, const float* __restrict__ bconv,
                            const float* __restrict__ W0, const float* __restrict__ b0,
                            const float* __restrict__ W1, const float* __restrict__ b1,
                            float* __restrict__ out, int N) {
    __shared__ float xs[64 * 101];  // padded rows: stride 101 avoids bank conflicts
    __shared__ float w0s[1000];
    __shared__ float w1s[10];
    __shared__ float b0s[10];
    __shared__ float bcs[100];
    int tid = threadIdx.x;
    int base = blockIdx.x * 64;

    for (int i = tid; i < 1000; i += 128) w0s[i] = W0[i];
    if (tid < 10) { w1s[tid] = W1[tid]; b0s[tid] = b0[tid]; }
    if (tid < 100) bcs[tid] = bconv[tid];
    __syncthreads();

    for (int i = tid; i < 6400; i += 128) {
        int r = i / 100, k = i - r * 100;
        int g = base + r;
        xs[r * 101 + k] = (g < N) ? (g_dinv[g] * acc[(size_t)g * 100 + k] + bcs[k]) : 0.f;
    }
    __syncthreads();

    if (tid < 64) {
        int g = base + tid;
        if (g < N) {
            float y[10];
#pragma unroll
            for (int j = 0; j < 10; j++) y[j] = b0s[j];
            const float* xr = xs + tid * 101;
            for (int k = 0; k < 100; k++) {
                float xv = xr[k];
#pragma unroll
                for (int j = 0; j < 10; j++) y[j] += xv * w0s[k * 10 + j];
            }
            float o = b1[0];
#pragma unroll
            for (int j = 0; j < 10; j++) o += fmaxf(y[j], 0.f) * w1s[j];
            out[g] = o;
        }
    }
}

extern "C" void kernel_launch(void* const* d_in, const int* in_sizes, int n_in,
                              void* d_out, int out_size) {
    const float* x   = (const float*)d_in[0];
    const int*   ei  = (const int*)d_in[1];
    const float* W0  = (const float*)d_in[2];
    const float* cb0 = (const float*)d_in[3];
    const float* W1  = (const float*)d_in[4];
    const float* cb1 = (const float*)d_in[5];
    const float* lW0 = (const float*)d_in[6];
    const float* lb0 = (const float*)d_in[7];
    const float* lW1 = (const float*)d_in[8];
    const float* lb1 = (const float*)d_in[9];
    float* out = (float*)d_out;

    int N = in_sizes[0] / 100;
    int E = in_sizes[1] / 2;
    const int* src = ei;
    const int* dst = ei + E;

    size_t gemm_smem = (10000 + 6400) * sizeof(float);  // 65.6 KB dynamic
    cudaFuncSetAttribute(gcn_gemm_kernel,
                         cudaFuncAttributeMaxDynamicSharedMemorySize, (int)gemm_smem);

    float *hs, *acc0, *acc1;
    cudaGetSymbolAddress((void**)&hs, g_hs);
    cudaGetSymbolAddress((void**)&acc0, g_acc0);
    cudaGetSymbolAddress((void**)&acc1, g_acc1);

    long n_elem = (long)N * 100;
    sumsq_partial_kernel<<<512, 256>>>(x, n_elem);
    sumsq_final_kernel<<<1, 256>>>(512);

    deg_init_kernel<<<(N + 255) / 256, 256>>>(N);
    deg_count_kernel<<<(E + 255) / 256, 256>>>(dst, E);
    dinv_kernel<<<(N + 255) / 256, 256>>>(N);

    int gblocks = (N + 63) / 64;
    long items = (long)E * 25;
    int sblocks = (int)((items + 255) / 256);

    // layer 0: hs0 = (dinv/||x||) * (x @ W0); acc0 = hs0 (self loop)
    gcn_gemm_kernel<<<gblocks, 256, gemm_smem>>>(x, W0, nullptr, 1, hs, acc0, N);
    scatter_kernel<<<sblocks, 256>>>(hs, acc0, src, dst, items);

    // layer 1: input = dinv*acc0 + cb0; hs1 = dinv * (input @ W1); acc1 = hs1
    gcn_gemm_kernel<<<gblocks, 256, gemm_smem>>>(acc0, W1, cb0, 0, hs, acc1, N);
    scatter_kernel<<<sblocks, 256>>>(hs, acc1, src, dst, items);

    // head: out[i] = relu((dinv*acc1 + cb1) @ lW0 + lb0) @ lW1 + lb1
    head_kernel<<<(N + 63) / 64, 128>>>(acc1, cb1, lW0, lb0, lW1, lb1, out, N);
}

// round 2
// speedup vs baseline: 1.4822x; 1.4822x over previous
#include <cuda_runtime.h>
#include <math.h>

// ---------------- scratch (no allocation allowed) ----------------
__device__ float g_hs[5000000];    // 50000 x 100
__device__ float g_acc0[5000000];
__device__ float g_acc1[5000000];
__device__ float g_dinv[50048];
__device__ int   g_cnt[50048];
__device__ int   g_rowptr[50049];
__device__ int   g_off[50049];
__device__ int   g_adj[800064];
__device__ int   g_bsum[256];
__device__ float g_partials[512];
__device__ float g_norm2;

// ---------------- ||x||^2 reduction ----------------
__global__ void sumsq_partial_kernel(const float* __restrict__ x, long n) {
    float s = 0.f;
    long stride = (long)gridDim.x * blockDim.x;
    for (long i = (long)blockIdx.x * blockDim.x + threadIdx.x; i < n; i += stride) {
        float v = x[i];
        s += v * v;
    }
    __shared__ float sm[256];
    sm[threadIdx.x] = s;
    __syncthreads();
    for (int o = 128; o > 0; o >>= 1) {
        if (threadIdx.x < o) sm[threadIdx.x] += sm[threadIdx.x + o];
        __syncthreads();
    }
    if (threadIdx.x == 0) g_partials[blockIdx.x] = sm[0];
}

__global__ void sumsq_final_kernel(int nb) {
    __shared__ float sm[256];
    float s = 0.f;
    for (int i = threadIdx.x; i < nb; i += 256) s += g_partials[i];
    sm[threadIdx.x] = s;
    __syncthreads();
    for (int o = 128; o > 0; o >>= 1) {
        if (threadIdx.x < o) sm[threadIdx.x] += sm[threadIdx.x + o];
        __syncthreads();
    }
    if (threadIdx.x == 0) g_norm2 = sm[0];
}

// ---------------- CSR build ----------------
__global__ void cnt_zero_kernel(int n) {
    int i = blockIdx.x * blockDim.x + threadIdx.x;
    if (i < n) g_cnt[i] = 0;
}

__global__ void hist_kernel(const int* __restrict__ dst, int E) {
    int i = blockIdx.x * blockDim.x + threadIdx.x;
    if (i < E) atomicAdd(&g_cnt[dst[i]], 1);
}

// per-block inclusive scan of 256 counts -> local exclusive into rowptr, block sum out
__global__ void scan1_kernel(int N) {
    __shared__ int sm[256];
    int node = blockIdx.x * 256 + threadIdx.x;
    int c = (node < N) ? g_cnt[node] : 0;
    sm[threadIdx.x] = c;
    __syncthreads();
    // Hillis-Steele inclusive scan
    for (int o = 1; o < 256; o <<= 1) {
        int v = (threadIdx.x >= o) ? sm[threadIdx.x - o] : 0;
        __syncthreads();
        sm[threadIdx.x] += v;
        __syncthreads();
    }
    if (node <= N) g_rowptr[node] = sm[threadIdx.x] - c;  // local exclusive
    if (threadIdx.x == 255) g_bsum[blockIdx.x] = sm[255];
}

__global__ void scan2_kernel(int nb) {
    __shared__ int sm[256];
    int c = (threadIdx.x < nb) ? g_bsum[threadIdx.x] : 0;
    sm[threadIdx.x] = c;
    __syncthreads();
    for (int o = 1; o < 256; o <<= 1) {
        int v = (threadIdx.x >= o) ? sm[threadIdx.x - o] : 0;
        __syncthreads();
        sm[threadIdx.x] += v;
        __syncthreads();
    }
    g_bsum[threadIdx.x] = sm[threadIdx.x] - c;  // exclusive
}

__global__ void scan3_kernel(int N, int E) {
    int node = blockIdx.x * 256 + threadIdx.x;
    if (node < N) {
        int r = g_rowptr[node] + g_bsum[blockIdx.x];
        g_rowptr[node] = r;
        g_off[node] = r;
        g_dinv[node] = rsqrtf((float)(g_cnt[node] + 1));  // +1 self-loop
    } else if (node == N) {
        g_rowptr[N] = E;
    }
}

__global__ void fill_kernel(const int* __restrict__ src, const int* __restrict__ dst, int E) {
    int i = blockIdx.x * blockDim.x + threadIdx.x;
    if (i < E) {
        int pos = atomicAdd(&g_off[dst[i]], 1);
        g_adj[pos] = src[i];
    }
}

// ---------------- GCN GEMM: hs = rowscale * ((xf(X)) @ W) ----------------
// layer0 (bin==nullptr): xf = X, rowscale = dinv[row]*rsqrt(norm2)
// layer1 (bin!=nullptr):  xf = dinv[row]*X + bin,  rowscale = dinv[row]
// 128 rows/block, 256 threads: thread = (ty: 2 rows ty & ty+64, tx: 25-col group)
__global__ void __launch_bounds__(256)
gcn_gemm_kernel(const float* __restrict__ X, const float* __restrict__ W,
                const float* __restrict__ bin, int use_norm,
                float* __restrict__ hs, int N) {
    extern __shared__ float smem[];
    float* sW = smem;          // 10000 floats
    float* sX = smem + 10000;  // 128*100 = 12800 floats
    int tid = threadIdx.x;
    int row0 = blockIdx.x * 128;

    for (int i = tid; i < 10000; i += 256) sW[i] = W[i];
    for (int i = tid; i < 12800; i += 256) {
        int r = i / 100, k = i - r * 100;
        int gr = row0 + r;
        float v = 0.f;
        if (gr < N) {
            v = X[(size_t)gr * 100 + k];
            if (bin) v = v * g_dinv[gr] + bin[k];
        }
        sX[i] = v;
    }
    __syncthreads();

    int tx = tid & 3, ty = tid >> 2;
    float a0[25], a1[25];
#pragma unroll
    for (int c = 0; c < 25; c++) { a0[c] = 0.f; a1[c] = 0.f; }
    const float* x0p = sX + ty * 100;
    const float* x1p = sX + (ty + 64) * 100;
    const float* wcol = sW + tx * 25;
#pragma unroll 2
    for (int k = 0; k < 100; k++) {
        float x0 = x0p[k];
        float x1 = x1p[k];
        const float* wr = wcol + k * 100;
#pragma unroll
        for (int c = 0; c < 25; c++) {
            float w = wr[c];
            a0[c] += x0 * w;
            a1[c] += x1 * w;
        }
    }

    float nrm = use_norm ? rsqrtf(g_norm2) : 1.0f;
    int gr0 = row0 + ty;
    int gr1 = row0 + ty + 64;
    if (gr0 < N) {
        float s = g_dinv[gr0] * nrm;
        size_t base = (size_t)gr0 * 100 + tx * 25;
#pragma unroll
        for (int c = 0; c < 25; c++) hs[base + c] = a0[c] * s;
    }
    if (gr1 < N) {
        float s = g_dinv[gr1] * nrm;
        size_t base = (size_t)gr1 * 100 + tx * 25;
#pragma unroll
        for (int c = 0; c < 25; c++) hs[base + c] = a1[c] * s;
    }
}

// ---------------- CSR aggregation: acc[i] = hs[i] + sum_{j in adj[i]} hs[j] ----------------
// one warp per node; lanes 0..24 each own one float4 (4 cols)
__global__ void __launch_bounds__(256)
agg_kernel(const float* __restrict__ hs, float* __restrict__ acc,
           const int* __restrict__ rowptr, const int* __restrict__ adj, int N) {
    int warp = (blockIdx.x * 256 + threadIdx.x) >> 5;
    int lane = threadIdx.x & 31;
    if (warp >= N) return;
    int node = warp;
    bool active = lane < 25;

    float4 sum = make_float4(0.f, 0.f, 0.f, 0.f);
    const float4* selfrow = (const float4*)(hs + (size_t)node * 100);
    if (active) sum = __ldg(selfrow + lane);  // self-loop

    int beg = rowptr[node];
    int end = rowptr[node + 1];
    for (int base = beg; base < end; base += 32) {
        int idx = base + lane;
        int my = (idx < end) ? adj[idx] : 0;
        int cnt = min(32, end - base);
#pragma unroll 4
        for (int j = 0; j < cnt; j++) {
            int s = __shfl_sync(0xffffffffu, my, j);
            if (active) {
                float4 v = __ldg((const float4*)(hs + (size_t)s * 100) + lane);
                sum.x += v.x; sum.y += v.y; sum.z += v.z; sum.w += v.w;
            }
        }
    }
    if (active) {
        float4* p = (float4*)(acc + (size_t)node * 100) + lane;
        *p = sum;
    }
}

// ---------------- MLP head ----------------
__global__ void head_kernel(const float* __restrict__ acc, const float* __restrict__ bconv,
                            const float* __restrict__ W0, const float* __restrict__ b0,
                            const float* __restrict__ W1, const float* __restrict__ b1,
                            float* __restrict__ out, int N) {
    __shared__ float xs[64 * 101];
    __shared__ float w0s[1000];
    __shared__ float w1s[10];
    __shared__ float b0s[10];
    __shared__ float bcs[100];
    int tid = threadIdx.x;
    int base = blockIdx.x * 64;

    for (int i = tid; i < 1000; i += 128) w0s[i] = W0[i];
    if (tid < 10) { w1s[tid] = W1[tid]; b0s[tid] = b0[tid]; }
    if (tid < 100) bcs[tid] = bconv[tid];
    __syncthreads();

    for (int i = tid; i < 6400; i += 128) {
        int r = i / 100, k = i - r * 100;
        int g = base + r;
        xs[r * 101 + k] = (g < N) ? (g_dinv[g] * acc[(size_t)g * 100 + k] + bcs[k]) : 0.f;
    }
    __syncthreads();

    if (tid < 64) {
        int g = base + tid;
        if (g < N) {
            float y[10];
#pragma unroll
            for (int j = 0; j < 10; j++) y[j] = b0s[j];
            const float* xr = xs + tid * 101;
            for (int k = 0; k < 100; k++) {
                float xv = xr[k];
#pragma unroll
                for (int j = 0; j < 10; j++) y[j] += xv * w0s[k * 10 + j];
            }
            float o = b1[0];
#pragma unroll
            for (int j = 0; j < 10; j++) o += fmaxf(y[j], 0.f) * w1s[j];
            out[g] = o;
        }
    }
}

extern "C" void kernel_launch(void* const* d_in, const int* in_sizes, int n_in,
                              void* d_out, int out_size) {
    const float* x   = (const float*)d_in[0];
    const int*   ei  = (const int*)d_in[1];
    const float* W0  = (const float*)d_in[2];
    const float* cb0 = (const float*)d_in[3];
    const float* W1  = (const float*)d_in[4];
    const float* cb1 = (const float*)d_in[5];
    const float* lW0 = (const float*)d_in[6];
    const float* lb0 = (const float*)d_in[7];
    const float* lW1 = (const float*)d_in[8];
    const float* lb1 = (const float*)d_in[9];
    float* out = (float*)d_out;

    int N = in_sizes[0] / 100;
    int E = in_sizes[1] / 2;
    const int* src = ei;
    const int* dst = ei + E;

    size_t gemm_smem = (10000 + 12800) * sizeof(float);  // 91.2 KB
    cudaFuncSetAttribute(gcn_gemm_kernel,
                         cudaFuncAttributeMaxDynamicSharedMemorySize, (int)gemm_smem);

    float *hs, *acc0, *acc1;
    int *rowptr, *adj;
    cudaGetSymbolAddress((void**)&hs, g_hs);
    cudaGetSymbolAddress((void**)&acc0, g_acc0);
    cudaGetSymbolAddress((void**)&acc1, g_acc1);
    cudaGetSymbolAddress((void**)&rowptr, g_rowptr);
    cudaGetSymbolAddress((void**)&adj, g_adj);

    long n_elem = (long)N * 100;
    sumsq_partial_kernel<<<512, 256>>>(x, n_elem);
    sumsq_final_kernel<<<1, 256>>>(512);

    // CSR build (by dst): histogram -> two-level scan -> fill
    int nscan = (N + 256) / 256;  // blocks covering nodes 0..N
    cnt_zero_kernel<<<(N + 255) / 256, 256>>>(N);
    hist_kernel<<<(E + 255) / 256, 256>>>(dst, E);
    scan1_kernel<<<nscan, 256>>>(N);
    scan2_kernel<<<1, 256>>>(nscan);
    scan3_kernel<<<nscan, 256>>>(N, E);
    fill_kernel<<<(E + 255) / 256, 256>>>(src, dst, E);

    int gblocks = (N + 127) / 128;
    int ablocks = (N + 7) / 8;  // 8 warps per block

    // layer 0
    gcn_gemm_kernel<<<gblocks, 256, gemm_smem>>>(x, W0, nullptr, 1, hs, N);
    agg_kernel<<<ablocks, 256>>>(hs, acc0, rowptr, adj, N);

    // layer 1
    gcn_gemm_kernel<<<gblocks, 256, gemm_smem>>>(acc0, W1, cb0, 0, hs, N);
    agg_kernel<<<ablocks, 256>>>(hs, acc1, rowptr, adj, N);

    // head
    head_kernel<<<(N + 63) / 64, 128>>>(acc1, cb1, lW0, lb0, lW1, lb1, out, N);
}

// round 3
// speedup vs baseline: 1.4894x; 1.0048x over previous
#include <cuda_runtime.h>
#include <cuda_fp16.h>
#include <math.h>

// ---------------- scratch (no allocation allowed) ----------------
__device__ __half g_hs[5000000];   // 50000 x 100, fp16
__device__ float  g_acc0[5000000];
__device__ float  g_acc1[5000000];
__device__ float  g_dinv[50048];
__device__ int    g_cnt[50048];
__device__ int    g_rowptr[50049];
__device__ int    g_off[50049];
__device__ int    g_adj[800064];
__device__ int    g_bsum[256];
__device__ float  g_partials[512];
__device__ float  g_norm2;

// ---------------- ||x||^2 reduction ----------------
__global__ void sumsq_partial_kernel(const float* __restrict__ x, long n) {
    float s = 0.f;
    long stride = (long)gridDim.x * blockDim.x;
    for (long i = (long)blockIdx.x * blockDim.x + threadIdx.x; i < n; i += stride) {
        float v = x[i];
        s += v * v;
    }
    __shared__ float sm[256];
    sm[threadIdx.x] = s;
    __syncthreads();
    for (int o = 128; o > 0; o >>= 1) {
        if (threadIdx.x < o) sm[threadIdx.x] += sm[threadIdx.x + o];
        __syncthreads();
    }
    if (threadIdx.x == 0) g_partials[blockIdx.x] = sm[0];
}

__global__ void sumsq_final_kernel(int nb) {
    __shared__ float sm[256];
    float s = 0.f;
    for (int i = threadIdx.x; i < nb; i += 256) s += g_partials[i];
    sm[threadIdx.x] = s;
    __syncthreads();
    for (int o = 128; o > 0; o >>= 1) {
        if (threadIdx.x < o) sm[threadIdx.x] += sm[threadIdx.x + o];
        __syncthreads();
    }
    if (threadIdx.x == 0) g_norm2 = sm[0];
}

// ---------------- CSR build ----------------
__global__ void cnt_zero_kernel(int n) {
    int i = blockIdx.x * blockDim.x + threadIdx.x;
    if (i < n) g_cnt[i] = 0;
}

__global__ void hist_kernel(const int* __restrict__ dst, int E) {
    int i = blockIdx.x * blockDim.x + threadIdx.x;
    if (i < E) atomicAdd(&g_cnt[dst[i]], 1);
}

__global__ void scan1_kernel(int N) {
    __shared__ int sm[256];
    int node = blockIdx.x * 256 + threadIdx.x;
    int c = (node < N) ? g_cnt[node] : 0;
    sm[threadIdx.x] = c;
    __syncthreads();
    for (int o = 1; o < 256; o <<= 1) {
        int v = (threadIdx.x >= o) ? sm[threadIdx.x - o] : 0;
        __syncthreads();
        sm[threadIdx.x] += v;
        __syncthreads();
    }
    if (node <= N) g_rowptr[node] = sm[threadIdx.x] - c;
    if (threadIdx.x == 255) g_bsum[blockIdx.x] = sm[255];
}

__global__ void scan2_kernel(int nb) {
    __shared__ int sm[256];
    int c = (threadIdx.x < nb) ? g_bsum[threadIdx.x] : 0;
    sm[threadIdx.x] = c;
    __syncthreads();
    for (int o = 1; o < 256; o <<= 1) {
        int v = (threadIdx.x >= o) ? sm[threadIdx.x - o] : 0;
        __syncthreads();
        sm[threadIdx.x] += v;
        __syncthreads();
    }
    g_bsum[threadIdx.x] = sm[threadIdx.x] - c;
}

__global__ void scan3_kernel(int N, int E) {
    int node = blockIdx.x * 256 + threadIdx.x;
    if (node < N) {
        int r = g_rowptr[node] + g_bsum[blockIdx.x];
        g_rowptr[node] = r;
        g_off[node] = r;
        g_dinv[node] = rsqrtf((float)(g_cnt[node] + 1));  // +1 self-loop
    } else if (node == N) {
        g_rowptr[N] = E;
    }
}

__global__ void fill_kernel(const int* __restrict__ src, const int* __restrict__ dst, int E) {
    int i = blockIdx.x * blockDim.x + threadIdx.x;
    if (i < E) {
        int pos = atomicAdd(&g_off[dst[i]], 1);
        g_adj[pos] = src[i];
    }
}

// ---------------- GEMM: hs = fp16((X + bin) @ W)  (pure, no scales) ----------------
// 352 rows/block, 352 threads; thread = (tx: 25-col group, ty: 4 rows ty+88i)
__global__ void __launch_bounds__(352)
gemm_kernel(const float* __restrict__ X, const float* __restrict__ W,
            const float* __restrict__ bin, __half* __restrict__ hs, int N) {
    extern __shared__ float smem[];
    float* sW = smem;           // 10000 floats
    float* sX = smem + 10000;   // 352*100 = 35200 floats
    int tid = threadIdx.x;
    int row0 = blockIdx.x * 352;

    for (int i = tid; i < 10000; i += 352) sW[i] = W[i];
    for (int i = tid; i < 35200; i += 352) {
        int r = i / 100, k = i - r * 100;
        int gr = row0 + r;
        float v = 0.f;
        if (gr < N) {
            v = X[(size_t)gr * 100 + k];
            if (bin) v += bin[k];
        }
        sX[i] = v;
    }
    __syncthreads();

    int tx = tid & 3, ty = tid >> 2;  // ty 0..87
    float a[4][25];
#pragma unroll
    for (int i = 0; i < 4; i++)
#pragma unroll
        for (int c = 0; c < 25; c++) a[i][c] = 0.f;

    const float* wbase = sW + tx * 25;
#pragma unroll 2
    for (int k = 0; k < 100; k++) {
        float xv[4];
#pragma unroll
        for (int i = 0; i < 4; i++) xv[i] = sX[(ty + 88 * i) * 100 + k];
        const float* wr = wbase + k * 100;
#pragma unroll
        for (int c = 0; c < 25; c++) {
            float w = wr[c];
#pragma unroll
            for (int i = 0; i < 4; i++) a[i][c] += xv[i] * w;
        }
    }

#pragma unroll
    for (int i = 0; i < 4; i++) {
        int gr = row0 + ty + 88 * i;
        if (gr < N) {
            __half* p = hs + (size_t)gr * 100 + tx * 25;
#pragma unroll
            for (int c = 0; c < 25; c++) p[c] = __float2half_rn(a[i][c]);
        }
    }
}

// ---------------- CSR agg: acc[i] = S*dinv_i*(dinv_i*hs_i + sum_j dinv_j*hs_j) ----------------
// one warp per node; lanes 0..24 own 4 cols each (uint2 = 4 halves); fp32 accum
__global__ void __launch_bounds__(256)
agg_kernel(const __half* __restrict__ hs, float* __restrict__ acc,
           const int* __restrict__ rowptr, const int* __restrict__ adj,
           int use_norm, int N) {
    int node = (blockIdx.x * 256 + threadIdx.x) >> 5;
    int lane = threadIdx.x & 31;
    if (node >= N) return;
    bool active = lane < 25;
    float di = g_dinv[node];

    float4 sum = make_float4(0.f, 0.f, 0.f, 0.f);
    if (active) {
        uint2 raw = __ldg((const uint2*)(hs + (size_t)node * 100) + lane);
        float2 f0 = __half22float2(*(const __half2*)&raw.x);
        float2 f1 = __half22float2(*(const __half2*)&raw.y);
        sum.x = di * f0.x; sum.y = di * f0.y;
        sum.z = di * f1.x; sum.w = di * f1.y;
    }

    int beg = rowptr[node];
    int end = rowptr[node + 1];
    for (int base = beg; base < end; base += 32) {
        int idx = base + lane;
        int my = (idx < end) ? adj[idx] : 0;
        float md = (idx < end) ? g_dinv[my] : 0.f;
        int cnt = min(32, end - base);
        // software-pipelined gather (MLP=2)
        int sj = __shfl_sync(0xffffffffu, my, 0);
        float dj = __shfl_sync(0xffffffffu, md, 0);
        uint2 v = make_uint2(0u, 0u);
        if (active) v = __ldg((const uint2*)(hs + (size_t)sj * 100) + lane);
        for (int j = 1; j <= cnt; j++) {
            int sn = __shfl_sync(0xffffffffu, my, j & 31);
            float dn = __shfl_sync(0xffffffffu, md, j & 31);
            uint2 vn = make_uint2(0u, 0u);
            if (active && j < cnt) vn = __ldg((const uint2*)(hs + (size_t)sn * 100) + lane);
            if (active) {
                float2 f0 = __half22float2(*(const __half2*)&v.x);
                float2 f1 = __half22float2(*(const __half2*)&v.y);
                sum.x += dj * f0.x; sum.y += dj * f0.y;
                sum.z += dj * f1.x; sum.w += dj * f1.y;
            }
            v = vn; dj = dn;
        }
    }

    if (active) {
        float os = di * (use_norm ? rsqrtf(g_norm2) : 1.0f);
        sum.x *= os; sum.y *= os; sum.z *= os; sum.w *= os;
        *((float4*)(acc + (size_t)node * 100) + lane) = sum;
    }
}

// ---------------- MLP head: out[i] = relu((acc+bconv) @ lW0 + lb0) @ lW1 + lb1 ----------------
__global__ void head_kernel(const float* __restrict__ acc, const float* __restrict__ bconv,
                            const float* __restrict__ W0, const float* __restrict__ b0,
                            const float* __restrict__ W1, const float* __restrict__ b1,
                            float* __restrict__ out, int N) {
    __shared__ float xs[64 * 101];
    __shared__ float w0s[1000];
    __shared__ float w1s[10];
    __shared__ float b0s[10];
    __shared__ float bcs[100];
    int tid = threadIdx.x;
    int base = blockIdx.x * 64;

    for (int i = tid; i < 1000; i += 128) w0s[i] = W0[i];
    if (tid < 10) { w1s[tid] = W1[tid]; b0s[tid] = b0[tid]; }
    if (tid < 100) bcs[tid] = bconv[tid];
    __syncthreads();

    for (int i = tid; i < 6400; i += 128) {
        int r = i / 100, k = i - r * 100;
        int g = base + r;
        xs[r * 101 + k] = (g < N) ? (acc[(size_t)g * 100 + k] + bcs[k]) : 0.f;
    }
    __syncthreads();

    if (tid < 64) {
        int g = base + tid;
        if (g < N) {
            float y[10];
#pragma unroll
            for (int j = 0; j < 10; j++) y[j] = b0s[j];
            const float* xr = xs + tid * 101;
            for (int k = 0; k < 100; k++) {
                float xv = xr[k];
#pragma unroll
                for (int j = 0; j < 10; j++) y[j] += xv * w0s[k * 10 + j];
            }
            float o = b1[0];
#pragma unroll
            for (int j = 0; j < 10; j++) o += fmaxf(y[j], 0.f) * w1s[j];
            out[g] = o;
        }
    }
}

extern "C" void kernel_launch(void* const* d_in, const int* in_sizes, int n_in,
                              void* d_out, int out_size) {
    const float* x   = (const float*)d_in[0];
    const int*   ei  = (const int*)d_in[1];
    const float* W0  = (const float*)d_in[2];
    const float* cb0 = (const float*)d_in[3];
    const float* W1  = (const float*)d_in[4];
    const float* cb1 = (const float*)d_in[5];
    const float* lW0 = (const float*)d_in[6];
    const float* lb0 = (const float*)d_in[7];
    const float* lW1 = (const float*)d_in[8];
    const float* lb1 = (const float*)d_in[9];
    float* out = (float*)d_out;

    int N = in_sizes[0] / 100;
    int E = in_sizes[1] / 2;
    const int* src = ei;
    const int* dst = ei + E;

    size_t gemm_smem = (10000 + 35200) * sizeof(float);  // 180.8 KB
    cudaFuncSetAttribute(gemm_kernel,
                         cudaFuncAttributeMaxDynamicSharedMemorySize, (int)gemm_smem);

    __half* hs;
    float *acc0, *acc1;
    int *rowptr, *adj;
    cudaGetSymbolAddress((void**)&hs, g_hs);
    cudaGetSymbolAddress((void**)&acc0, g_acc0);
    cudaGetSymbolAddress((void**)&acc1, g_acc1);
    cudaGetSymbolAddress((void**)&rowptr, g_rowptr);
    cudaGetSymbolAddress((void**)&adj, g_adj);

    // fork: branch A (norm + CSR build) on s2, branch B (GEMM0) on default stream
    cudaStream_t s2;
    cudaStreamCreateWithFlags(&s2, cudaStreamNonBlocking);
    cudaEvent_t ev0, ev1;
    cudaEventCreateWithFlags(&ev0, cudaEventDisableTiming);
    cudaEventCreateWithFlags(&ev1, cudaEventDisableTiming);

    cudaEventRecord(ev0, 0);
    cudaStreamWaitEvent(s2, ev0, 0);

    // ----- branch A -----
    long n_elem = (long)N * 100;
    sumsq_partial_kernel<<<512, 256, 0, s2>>>(x, n_elem);
    sumsq_final_kernel<<<1, 256, 0, s2>>>(512);
    int nscan = (N + 256) / 256;
    cnt_zero_kernel<<<(N + 255) / 256, 256, 0, s2>>>(N);
    hist_kernel<<<(E + 255) / 256, 256, 0, s2>>>(dst, E);
    scan1_kernel<<<nscan, 256, 0, s2>>>(N);
    scan2_kernel<<<1, 256, 0, s2>>>(nscan);
    scan3_kernel<<<nscan, 256, 0, s2>>>(N, E);
    fill_kernel<<<(E + 255) / 256, 256, 0, s2>>>(src, dst, E);
    cudaEventRecord(ev1, s2);

    // ----- branch B -----
    int gblocks = (N + 351) / 352;
    gemm_kernel<<<gblocks, 352, gemm_smem>>>(x, W0, nullptr, hs, N);

    // join
    cudaStreamWaitEvent(0, ev1, 0);

    int ablocks = (N + 7) / 8;  // 8 warps per block
    agg_kernel<<<ablocks, 256>>>(hs, acc0, rowptr, adj, 1, N);
    gemm_kernel<<<gblocks, 352, gemm_smem>>>(acc0, W1, cb0, hs, N);
    agg_kernel<<<ablocks, 256>>>(hs, acc1, rowptr, adj, 0, N);
    head_kernel<<<(N + 63) / 64, 128>>>(acc1, cb1, lW0, lb0, lW1, lb1, out, N);
}